// round 17
// baseline (speedup 1.0000x reference)
#include <cuda_runtime.h>
#include <cstdint>

// Problem shape (fixed by reference setup_inputs)
#define B_ 8
#define C_ 128
#define H_ 256
#define W_ 256
#define N_ (H_ * W_)     // 65536 pixels per image
#define S_ 1024          // segments per image
#define PLANE4 (N_ / 4)  // plane stride in float4 units = 16384

#define ACC_ELEMS (B_ * S_ * C_)      // 1M floats per replica
#define F4_TOTAL (ACC_ELEMS / 4)      // 262144 float4 per replica
#define F4_HALF  (F4_TOTAL / 2)

// TWO accumulator replicas (measured best): scatter CTAs alternate by chunk
// parity. Zero at static init; finalize re-zeroes both (and g_counts),
// preserving the zero-at-entry invariant across graph replays.
__device__ float g_accum0[ACC_ELEMS];
__device__ float g_accum1[ACC_ELEMS];
__device__ float g_counts[B_ * S_];

// ---------------------------------------------------------------------------
// Scatter + fused count — round-14 best configuration (scatter ~103.3us).
// grid: (16 pixel-chunks, C_/4 channel-groups, B_), block 256.
// Per thread, per group of 4 consecutive pixels:
//   1x LDG.128 labels + 4x LDG.128 planes + 4x red.global.add.v4.f32
// Replica = chunk & 1. cg==0 blocks histogram their labels into g_counts.
// (Settled by experiment: do NOT change grid shape, occupancy caps, or
// label-sharing — all measured slower.)
// ---------------------------------------------------------------------------
__global__ void __launch_bounds__(256) scatter_kernel(
    const float* __restrict__ in,
    const int* __restrict__ labels)
{
    __shared__ int hist[S_];

    const int b     = blockIdx.z;
    const int cg    = blockIdx.y;    // channel group of 4
    const int chunk = blockIdx.x;    // 4096-pixel spatial chunk
    const int t     = threadIdx.x;
    const bool do_count = (cg == 0);   // uniform per block

    if (do_count) {
        for (int i = t; i < S_; i += 256) hist[i] = 0;
        __syncthreads();
    }

    const float4* p0 = reinterpret_cast<const float4*>(
                           in + ((size_t)b * C_ + (size_t)cg * 4) * N_)
                       + chunk * 1024;
    const int4* lab4 = reinterpret_cast<const int4*>(
                           labels + (size_t)b * N_ + chunk * 4096);
    float* const rep = (chunk & 1) ? g_accum1 : g_accum0;
    float* ob = rep + (size_t)b * S_ * C_ + cg * 4;

    #pragma unroll
    for (int g = 0; g < 4; g++) {
        const int idx = g * 256 + t;               // float4 index within chunk
        const float4 x0 = p0[idx];                 // channel cg*4+0, pixels p..p+3
        const float4 x1 = p0[PLANE4     + idx];    // channel cg*4+1
        const float4 x2 = p0[2 * PLANE4 + idx];    // channel cg*4+2
        const float4 x3 = p0[3 * PLANE4 + idx];    // channel cg*4+3
        const int4 sg = lab4[idx];

        if (do_count) {
            atomicAdd(&hist[sg.x], 1);
            atomicAdd(&hist[sg.y], 1);
            atomicAdd(&hist[sg.z], 1);
            atomicAdd(&hist[sg.w], 1);
        }

        float* a0 = ob + (size_t)sg.x * C_;
        float* a1 = ob + (size_t)sg.y * C_;
        float* a2 = ob + (size_t)sg.z * C_;
        float* a3 = ob + (size_t)sg.w * C_;
        asm volatile("red.global.add.v4.f32 [%0], {%1, %2, %3, %4};"
                     :: "l"(a0), "f"(x0.x), "f"(x1.x), "f"(x2.x), "f"(x3.x) : "memory");
        asm volatile("red.global.add.v4.f32 [%0], {%1, %2, %3, %4};"
                     :: "l"(a1), "f"(x0.y), "f"(x1.y), "f"(x2.y), "f"(x3.y) : "memory");
        asm volatile("red.global.add.v4.f32 [%0], {%1, %2, %3, %4};"
                     :: "l"(a2), "f"(x0.z), "f"(x1.z), "f"(x2.z), "f"(x3.z) : "memory");
        asm volatile("red.global.add.v4.f32 [%0], {%1, %2, %3, %4};"
                     :: "l"(a3), "f"(x0.w), "f"(x1.w), "f"(x2.w), "f"(x3.w) : "memory");
    }

    if (do_count) {
        __syncthreads();
        for (int i = t; i < S_; i += 256) {
            int v = hist[i];
            if (v) atomicAdd(&g_counts[b * S_ + i], (float)v);
        }
    }
}

// ---------------------------------------------------------------------------
// Finalize, ILP-oriented: each thread owns TWO float4s (gt, gt+F4_HALF).
// All 6 independent loads (2 counts + 4 acc) issue before any dependent
// math — halves exposed L2 latency vs the 1-f4 version (7.8us, occ 41%,
// latency-bound). Warp-local count zeroing: for each half, the 32 readers
// of count word (idx>>5) are exactly this warp's lanes at that half.
// grid 512 x block 256.
// ---------------------------------------------------------------------------
__global__ void __launch_bounds__(256) finalize_kernel(float4* __restrict__ out) {
    const int gt = blockIdx.x * blockDim.x + threadIdx.x;   // 0..F4_HALF-1
    float4* acc0 = reinterpret_cast<float4*>(g_accum0);
    float4* acc1 = reinterpret_cast<float4*>(g_accum1);

    const int iA = gt;
    const int iB = gt + F4_HALF;

    // issue all independent loads up front
    const float cA = g_counts[iA >> 5];
    const float cB = g_counts[iB >> 5];
    const float4 uA = acc0[iA];
    const float4 wA = acc1[iA];
    const float4 uB = acc0[iB];
    const float4 wB = acc1[iB];

    __syncwarp();
    if ((threadIdx.x & 31) == 0) {
        g_counts[iA >> 5] = 0.0f;       // restore zero invariant
        g_counts[iB >> 5] = 0.0f;
    }

    const float sA = 1.0f / fmaxf(cA, 1.0f);
    const float sB = 1.0f / fmaxf(cB, 1.0f);
    float4 vA, vB;
    vA.x = (uA.x + wA.x) * sA;  vA.y = (uA.y + wA.y) * sA;
    vA.z = (uA.z + wA.z) * sA;  vA.w = (uA.w + wA.w) * sA;
    vB.x = (uB.x + wB.x) * sB;  vB.y = (uB.y + wB.y) * sB;
    vB.z = (uB.z + wB.z) * sB;  vB.w = (uB.w + wB.w) * sB;

    out[iA] = vA;
    out[iB] = vB;
    const float4 z = make_float4(0.f, 0.f, 0.f, 0.f);
    acc0[iA] = z;  acc1[iA] = z;        // restore zero invariant
    acc0[iB] = z;  acc1[iB] = z;
}

// ---------------------------------------------------------------------------
// kernel_launch: scatter -> finalize.  2 launches, graph-capturable.
// ---------------------------------------------------------------------------
extern "C" void kernel_launch(void* const* d_in, const int* in_sizes, int n_in,
                              void* d_out, int out_size) {
    const float* in     = (const float*)d_in[0];
    const int*   labels = (const int*)d_in[1];

    scatter_kernel<<<dim3(16, C_ / 4, B_), 256>>>(in, labels);

    finalize_kernel<<<F4_HALF / 256, 256>>>((float4*)d_out);
}